// round 6
// baseline (speedup 1.0000x reference)
#include <cuda_runtime.h>
#include <cstdint>

#define B_    256
#define T_    1024
#define IN_   3
#define HID_  512
#define RANK_ 4
#define OUT_  3

#define TPB 64    // 2 warps per block, EACH warp = one full batch (no loop barriers)
#define BPB 2
#define UPT 16    // units per lane: j = 128*c + 4*lane + 2*e  (c=0..3 chunk, e=0..1 pair)

typedef unsigned long long u64;

#define C2LOG2E 2.885390081777927f   // 2*log2(e), folded into U', Win', bin'

__device__ __forceinline__ u64 fma2(u64 a, u64 b, u64 c) {
    u64 d;
    asm("fma.rn.f32x2 %0, %1, %2, %3;" : "=l"(d) : "l"(a), "l"(b), "l"(c));
    return d;
}
__device__ __forceinline__ u64 pack2(float lo, float hi) {
    u64 r;
    asm("mov.b64 %0, {%1, %2};" : "=l"(r) : "f"(lo), "f"(hi));
    return r;
}
__device__ __forceinline__ void unpack2(u64 v, float& lo, float& hi) {
    asm("mov.b64 {%0, %1}, %2;" : "=f"(lo), "=f"(hi) : "l"(v));
}
__device__ __forceinline__ float hadd2(u64 v) {
    float lo, hi;
    unpack2(v, lo, hi);
    return lo + hi;
}

// tanh with 2*log2(e) prescale folded into the argument:
// tanh(a) = 1 - 2/(2^{a'} + 1), a' = 2*log2(e)*a. Saturates correctly; err ~1e-7.
__device__ __forceinline__ float tanh_pre(float ap) {
    float e;
    asm("ex2.approx.f32 %0, %1;" : "=f"(e) : "f"(ap));
    float r;
    asm("rcp.approx.f32 %0, %1;" : "=f"(r) : "f"(e + 1.0f));
    return fmaf(-2.0f, r, 1.0f);
}

__global__ void __launch_bounds__(TPB, 1)
low_rank_rnn_kernel(const float* __restrict__ x,
                    const float* __restrict__ hidden,
                    const float* __restrict__ U,
                    const float* __restrict__ V,
                    const float* __restrict__ Win,
                    const float* __restrict__ bin,
                    const float* __restrict__ Wout,
                    const float* __restrict__ bout,
                    float* __restrict__ out,    // [B,T,OUT]
                    float* __restrict__ hlast,  // [B,HID]
                    float* __restrict__ rout)   // [B,T,HID]
{
    const int tid  = threadIdx.x;
    const int wid  = tid >> 5;
    const int lane = tid & 31;
    const int b    = blockIdx.x * BPB + wid;

    // smem: per-batch x + shared weight tables in lane-major pair layout
    __shared__ float xs[BPB][T_ * IN_];       // 24 KB
    __shared__ u64 vS [RANK_][8][32];         // 8 KB   V pairs
    __shared__ u64 woS[OUT_ ][8][32];         // 6 KB   Wout pairs
    __shared__ u64 wiS[IN_  ][8][32];         // 6 KB   Win' pairs (prescaled)

    // ---- cooperative smem init ----
    {
        const float4* xb4 = (const float4*)(x + (size_t)blockIdx.x * BPB * (T_ * IN_));
        float4* xs4 = (float4*)&xs[0][0];
        #pragma unroll 1
        for (int i = tid; i < (BPB * T_ * IN_) / 4; i += TPB) xs4[i] = xb4[i];

        // pair pIdx in [0,256): j = 2*pIdx; j = 128c + 4L + 2e
        #pragma unroll 1
        for (int pIdx = tid; pIdx < HID_ / 2; pIdx += TPB) {
            int j  = 2 * pIdx;
            int e  = (j >> 1) & 1;
            int L  = (j >> 2) & 31;
            int c  = j >> 7;
            int pp = 2 * c + e;
            #pragma unroll
            for (int r = 0; r < RANK_; r++)
                vS[r][pp][L] = pack2(V[r * HID_ + j], V[r * HID_ + j + 1]);
            #pragma unroll
            for (int o = 0; o < OUT_; o++)
                woS[o][pp][L] = pack2(Wout[o * HID_ + j], Wout[o * HID_ + j + 1]);
            #pragma unroll
            for (int i = 0; i < IN_; i++)
                wiS[i][pp][L] = pack2(C2LOG2E * Win[j * IN_ + i],
                                      C2LOG2E * Win[(j + 1) * IN_ + i]);
        }
    }

    // ---- register weights: U' (prescaled) and bin' only ----
    u64 up[RANK_][8], bip[8];
    #pragma unroll
    for (int pp = 0; pp < 8; pp++) {
        int j = ((pp >> 1) << 7) + 4 * lane + ((pp & 1) << 1);
        #pragma unroll
        for (int r = 0; r < RANK_; r++)
            up[r][pp] = pack2(C2LOG2E * U[r * HID_ + j], C2LOG2E * U[r * HID_ + j + 1]);
        bip[pp] = pack2(C2LOG2E * bin[j], C2LOG2E * bin[j + 1]);
    }
    const float bo0 = bout[0], bo1 = bout[1], bo2 = bout[2];

    __syncthreads();   // one-time: smem tables + xs ready; warps independent after

    // ---- initial p = V @ h0 (warp-local 5-level butterfly) ----
    float p0, p1, p2, p3;
    {
        u64 acc[RANK_] = {0ull, 0ull, 0ull, 0ull};
        #pragma unroll
        for (int c = 0; c < 4; c++) {
            float4 h4 = *(const float4*)(hidden + (size_t)b * HID_ + 128 * c + 4 * lane);
            u64 hp0 = pack2(h4.x, h4.y);
            u64 hp1 = pack2(h4.z, h4.w);
            #pragma unroll
            for (int r = 0; r < RANK_; r++) {
                acc[r] = fma2(hp0, vS[r][2 * c][lane], acc[r]);
                acc[r] = fma2(hp1, vS[r][2 * c + 1][lane], acc[r]);
            }
        }
        float s0 = hadd2(acc[0]), s1 = hadd2(acc[1]);
        float s2 = hadd2(acc[2]), s3 = hadd2(acc[3]);
        #pragma unroll
        for (int off = 16; off > 0; off >>= 1) {
            s0 += __shfl_xor_sync(0xffffffffu, s0, off);
            s1 += __shfl_xor_sync(0xffffffffu, s1, off);
            s2 += __shfl_xor_sync(0xffffffffu, s2, off);
            s3 += __shfl_xor_sync(0xffffffffu, s3, off);
        }
        p0 = s0; p1 = s1; p2 = s2; p3 = s3;
    }

    // ---- iw' for t=0 ----
    u64 iw[8];
    {
        float xv0 = xs[wid][0], xv1 = xs[wid][1], xv2 = xs[wid][2];
        u64 X0 = pack2(xv0, xv0), X1 = pack2(xv1, xv1), X2 = pack2(xv2, xv2);
        #pragma unroll
        for (int pp = 0; pp < 8; pp++)
            iw[pp] = fma2(X2, wiS[2][pp][lane],
                     fma2(X1, wiS[1][pp][lane],
                     fma2(X0, wiS[0][pp][lane], bip[pp])));
    }

    float* routb = rout + (size_t)b * T_ * HID_;
    float* outb  = out  + (size_t)b * T_ * OUT_;

    #pragma unroll 1
    for (int t = 0; t < T_; t++) {
        u64 pB0 = pack2(p0, p0), pB1 = pack2(p1, p1);
        u64 pB2 = pack2(p2, p2), pB3 = pack2(p3, p3);

        u64 pa[RANK_] = {0ull, 0ull, 0ull, 0ull};
        u64 qa[OUT_]  = {0ull, 0ull, 0ull};

        #pragma unroll
        for (int c = 0; c < 4; c++) {
            float hc[4];
            #pragma unroll
            for (int e = 0; e < 2; e++) {
                const int pp = 2 * c + e;
                u64 a = fma2(pB3, up[3][pp], fma2(pB2, up[2][pp],
                        fma2(pB1, up[1][pp], fma2(pB0, up[0][pp], iw[pp]))));
                float a0, a1;
                unpack2(a, a0, a1);
                float h0 = tanh_pre(a0);
                float h1 = tanh_pre(a1);
                hc[2 * e]     = h0;
                hc[2 * e + 1] = h1;
                u64 hp = pack2(h0, h1);
                #pragma unroll
                for (int r = 0; r < RANK_; r++) pa[r] = fma2(hp, vS[r][pp][lane], pa[r]);
                #pragma unroll
                for (int o = 0; o < OUT_; o++)  qa[o] = fma2(hp, woS[o][pp][lane], qa[o]);
            }
            // coalesced: 32 lanes x 16B at stride 16B = contiguous 512B
            *(float4*)(routb + (size_t)t * HID_ + 128 * c + 4 * lane) =
                make_float4(hc[0], hc[1], hc[2], hc[3]);
        }

        float s0 = hadd2(pa[0]), s1 = hadd2(pa[1]);
        float s2 = hadd2(pa[2]), s3 = hadd2(pa[3]);
        float q0 = hadd2(qa[0]), q1 = hadd2(qa[1]), q2 = hadd2(qa[2]);

        // prefetch next iw' (fills SHFL-wait shadow)
        if (t + 1 < T_) {
            float xv0 = xs[wid][3 * (t + 1) + 0];
            float xv1 = xs[wid][3 * (t + 1) + 1];
            float xv2 = xs[wid][3 * (t + 1) + 2];
            u64 X0 = pack2(xv0, xv0), X1 = pack2(xv1, xv1), X2 = pack2(xv2, xv2);
            #pragma unroll
            for (int pp = 0; pp < 8; pp++)
                iw[pp] = fma2(X2, wiS[2][pp][lane],
                         fma2(X1, wiS[1][pp][lane],
                         fma2(X0, wiS[0][pp][lane], bip[pp])));
        }

        // warp-local 5-level butterfly over 7 values — no barrier, no smem
        #pragma unroll
        for (int off = 16; off > 0; off >>= 1) {
            s0 += __shfl_xor_sync(0xffffffffu, s0, off);
            s1 += __shfl_xor_sync(0xffffffffu, s1, off);
            s2 += __shfl_xor_sync(0xffffffffu, s2, off);
            s3 += __shfl_xor_sync(0xffffffffu, s3, off);
            q0 += __shfl_xor_sync(0xffffffffu, q0, off);
            q1 += __shfl_xor_sync(0xffffffffu, q1, off);
            q2 += __shfl_xor_sync(0xffffffffu, q2, off);
        }
        p0 = s0; p1 = s1; p2 = s2; p3 = s3;

        if (lane == 0) {
            outb[(size_t)t * OUT_ + 0] = q0 + bo0;
            outb[(size_t)t * OUT_ + 1] = q1 + bo1;
            outb[(size_t)t * OUT_ + 2] = q2 + bo2;
        }
    }

    // h_last: read back the t = T-1 row we just wrote (same thread, visible)
    #pragma unroll
    for (int c = 0; c < 4; c++) {
        float4 h4 = *(const float4*)(routb + (size_t)(T_ - 1) * HID_ + 128 * c + 4 * lane);
        *(float4*)(hlast + (size_t)b * HID_ + 128 * c + 4 * lane) = h4;
    }
}

extern "C" void kernel_launch(void* const* d_in, const int* in_sizes, int n_in,
                              void* d_out, int out_size) {
    const float* x      = (const float*)d_in[0];
    const float* hidden = (const float*)d_in[1];
    const float* U      = (const float*)d_in[2];
    const float* V      = (const float*)d_in[3];
    const float* Win    = (const float*)d_in[4];
    const float* bin    = (const float*)d_in[5];
    const float* Wout   = (const float*)d_in[6];
    const float* bout   = (const float*)d_in[7];

    float* out   = (float*)d_out;                       // [B,T,OUT]
    float* hlast = out   + (size_t)B_ * T_ * OUT_;      // [B,HID]
    float* rout  = hlast + (size_t)B_ * HID_;           // [B,T,HID]

    low_rank_rnn_kernel<<<B_ / BPB, TPB>>>(x, hidden, U, V, Win, bin, Wout, bout,
                                           out, hlast, rout);
}

// round 7
// speedup vs baseline: 1.6124x; 1.6124x over previous
#include <cuda_runtime.h>
#include <cstdint>

#define B_    256
#define T_    1024
#define IN_   3
#define HID_  512
#define RANK_ 4
#define OUT_  3

#define TPB 64    // 2 warps, one batch per block (grid = 256 -> 2 blocks/SM co-resident)
#define UPT 8     // hidden units per thread

typedef unsigned long long u64;

#define C2LOG2E 2.885390081777927f   // 2*log2(e), folded into U', Win', bin'

__device__ __forceinline__ u64 fma2(u64 a, u64 b, u64 c) {
    u64 d;
    asm("fma.rn.f32x2 %0, %1, %2, %3;" : "=l"(d) : "l"(a), "l"(b), "l"(c));
    return d;
}
__device__ __forceinline__ u64 pack2(float lo, float hi) {
    u64 r;
    asm("mov.b64 %0, {%1, %2};" : "=l"(r) : "f"(lo), "f"(hi));
    return r;
}
__device__ __forceinline__ void unpack2(u64 v, float& lo, float& hi) {
    asm("mov.b64 {%0, %1}, %2;" : "=f"(lo), "=f"(hi) : "l"(v));
}
__device__ __forceinline__ float hadd2(u64 v) {
    float lo, hi;
    unpack2(v, lo, hi);
    return lo + hi;
}

// tanh with 2*log2(e) prescale folded into the argument:
// tanh(a) = 1 - 2/(2^{a'} + 1). Saturates correctly at +-inf; abs err ~1e-7.
__device__ __forceinline__ float tanh_pre(float ap) {
    float e;
    asm("ex2.approx.f32 %0, %1;" : "=f"(e) : "f"(ap));
    float r;
    asm("rcp.approx.f32 %0, %1;" : "=f"(r) : "f"(e + 1.0f));
    return fmaf(-2.0f, r, 1.0f);
}

__global__ void __launch_bounds__(TPB)
low_rank_rnn_kernel(const float* __restrict__ x,
                    const float* __restrict__ hidden,
                    const float* __restrict__ U,
                    const float* __restrict__ V,
                    const float* __restrict__ Win,
                    const float* __restrict__ bin,
                    const float* __restrict__ Wout,
                    const float* __restrict__ bout,
                    float* __restrict__ out,    // [B,T,OUT]
                    float* __restrict__ hlast,  // [B,HID]
                    float* __restrict__ rout)   // [B,T,HID]
{
    const int b    = blockIdx.x;
    const int tid  = threadIdx.x;
    const int wid  = tid >> 5;
    const int lane = tid & 31;
    const int j0   = tid * UPT;
    const int grp  = tid >> 3;     // 0..7: value group (0-3 -> p, 4-6 -> q, 7 pad)
    const int k8   = tid & 7;      // lane within group

    __shared__ float xs[T_ * IN_];                    // 12 KB
    __shared__ __align__(16) float red[2][64][8];     // per-lane partials (ping-pong)
    __shared__ __align__(16) float fin[2][8];         // reduced {p0..p3,q0..q2,pad}

    // ---- stage x[b] (vectorized) ----
    {
        const float4* xb4 = (const float4*)(x + (size_t)b * (T_ * IN_));
        float4* xs4 = (float4*)xs;
        #pragma unroll 1
        for (int i = tid; i < (T_ * IN_) / 4; i += TPB) xs4[i] = xb4[i];
    }

    // ---- per-thread register weights (U', Win', bin' prescaled) ----
    u64 up[RANK_][4], vp[RANK_][4], wop[OUT_][4], wip[IN_][4], bip[4];
    #pragma unroll
    for (int r = 0; r < RANK_; r++)
        #pragma unroll
        for (int pp = 0; pp < 4; pp++) {
            int j = j0 + 2 * pp;
            up[r][pp] = pack2(C2LOG2E * U[r * HID_ + j], C2LOG2E * U[r * HID_ + j + 1]);
            vp[r][pp] = pack2(V[r * HID_ + j], V[r * HID_ + j + 1]);
        }
    #pragma unroll
    for (int o = 0; o < OUT_; o++)
        #pragma unroll
        for (int pp = 0; pp < 4; pp++) {
            int j = j0 + 2 * pp;
            wop[o][pp] = pack2(Wout[o * HID_ + j], Wout[o * HID_ + j + 1]);
        }
    #pragma unroll
    for (int i = 0; i < IN_; i++)
        #pragma unroll
        for (int pp = 0; pp < 4; pp++) {
            int j = j0 + 2 * pp;
            wip[i][pp] = pack2(C2LOG2E * Win[j * IN_ + i], C2LOG2E * Win[(j + 1) * IN_ + i]);
        }
    #pragma unroll
    for (int pp = 0; pp < 4; pp++) {
        int j = j0 + 2 * pp;
        bip[pp] = pack2(C2LOG2E * bin[j], C2LOG2E * bin[j + 1]);
    }
    float bo0 = 0.f, bo1 = 0.f, bo2 = 0.f;
    if (tid == 0) { bo0 = bout[0]; bo1 = bout[1]; bo2 = bout[2]; }

    float h[UPT];
    #pragma unroll
    for (int k = 0; k < UPT; k++) h[k] = hidden[(size_t)b * HID_ + j0 + k];

    // ---- initial p = V @ h (one-time; uses fin[1] scratch) ----
    float p0, p1, p2, p3;
    {
        u64 acc[RANK_] = {0ull, 0ull, 0ull, 0ull};
        #pragma unroll
        for (int pp = 0; pp < 4; pp++) {
            u64 hp = pack2(h[2 * pp], h[2 * pp + 1]);
            #pragma unroll
            for (int r = 0; r < RANK_; r++) acc[r] = fma2(hp, vp[r][pp], acc[r]);
        }
        float s0 = hadd2(acc[0]), s1 = hadd2(acc[1]);
        float s2 = hadd2(acc[2]), s3 = hadd2(acc[3]);
        #pragma unroll
        for (int off = 16; off > 0; off >>= 1) {
            s0 += __shfl_xor_sync(0xffffffffu, s0, off);
            s1 += __shfl_xor_sync(0xffffffffu, s1, off);
            s2 += __shfl_xor_sync(0xffffffffu, s2, off);
            s3 += __shfl_xor_sync(0xffffffffu, s3, off);
        }
        if (lane == 0)
            *(float4*)&red[1][wid][0] = make_float4(s0, s1, s2, s3);
    }
    __syncthreads();   // also covers xs staging
    {
        float4 a0 = *(const float4*)&red[1][0][0];
        float4 a1 = *(const float4*)&red[1][1][0];
        p0 = a0.x + a1.x; p1 = a0.y + a1.y;
        p2 = a0.z + a1.z; p3 = a0.w + a1.w;
    }
    __syncthreads();   // red[1] consumed before loop t=1 overwrites it

    // ---- iw' for t=0 ----
    u64 iw[4];
    {
        float xv0 = xs[0], xv1 = xs[1], xv2 = xs[2];
        u64 X0 = pack2(xv0, xv0), X1 = pack2(xv1, xv1), X2 = pack2(xv2, xv2);
        #pragma unroll
        for (int pp = 0; pp < 4; pp++)
            iw[pp] = fma2(X2, wip[2][pp], fma2(X1, wip[1][pp], fma2(X0, wip[0][pp], bip[pp])));
    }

    float* routb = rout + (size_t)b * T_ * HID_;
    float* outb  = out  + (size_t)b * T_ * OUT_;

    #pragma unroll 1
    for (int t = 0; t < T_; t++) {
        const int pb = t & 1;

        // a' = iw' + U'^T p ; h = tanh ; partials
        u64 pB0 = pack2(p0, p0), pB1 = pack2(p1, p1);
        u64 pB2 = pack2(p2, p2), pB3 = pack2(p3, p3);

        u64 pa[RANK_] = {0ull, 0ull, 0ull, 0ull};
        u64 qa[OUT_]  = {0ull, 0ull, 0ull};

        #pragma unroll
        for (int pp = 0; pp < 4; pp++) {
            u64 a = fma2(pB3, up[3][pp], fma2(pB2, up[2][pp],
                    fma2(pB1, up[1][pp], fma2(pB0, up[0][pp], iw[pp]))));
            float a0, a1;
            unpack2(a, a0, a1);
            float h0 = tanh_pre(a0);
            float h1 = tanh_pre(a1);
            h[2 * pp]     = h0;
            h[2 * pp + 1] = h1;
            u64 hp = pack2(h0, h1);
            #pragma unroll
            for (int r = 0; r < RANK_; r++) pa[r] = fma2(hp, vp[r][pp], pa[r]);
            #pragma unroll
            for (int o = 0; o < OUT_; o++)  qa[o] = fma2(hp, wop[o][pp], qa[o]);
        }

        // per-lane scalar partials -> smem (NO butterfly)
        *(float4*)&red[pb][tid][0] =
            make_float4(hadd2(pa[0]), hadd2(pa[1]), hadd2(pa[2]), hadd2(pa[3]));
        *(float4*)&red[pb][tid][4] =
            make_float4(hadd2(qa[0]), hadd2(qa[1]), hadd2(qa[2]), 0.f);

        // coalesced r_out store (off the dependency chain)
        *(float4*)(routb + (size_t)t * HID_ + j0)     = make_float4(h[0], h[1], h[2], h[3]);
        *(float4*)(routb + (size_t)t * HID_ + j0 + 4) = make_float4(h[4], h[5], h[6], h[7]);

        // prefetch next iw' (fills barrier shadow)
        if (t + 1 < T_) {
            float xv0 = xs[3 * (t + 1) + 0];
            float xv1 = xs[3 * (t + 1) + 1];
            float xv2 = xs[3 * (t + 1) + 2];
            u64 X0 = pack2(xv0, xv0), X1 = pack2(xv1, xv1), X2 = pack2(xv2, xv2);
            #pragma unroll
            for (int pp = 0; pp < 4; pp++)
                iw[pp] = fma2(X2, wip[2][pp], fma2(X1, wip[1][pp], fma2(X0, wip[0][pp], bip[pp])));
        }

        __syncthreads();   // bar1: all partials visible

        // stage 2: group 'grp' reduces 64 partials of value 'grp'
        // lane k8 sums 8 strided rows, then 3-level shfl within the 8-lane group
        float acc;
        {
            float v0 = red[pb][k8 +  0][grp];
            float v1 = red[pb][k8 +  8][grp];
            float v2 = red[pb][k8 + 16][grp];
            float v3 = red[pb][k8 + 24][grp];
            float v4 = red[pb][k8 + 32][grp];
            float v5 = red[pb][k8 + 40][grp];
            float v6 = red[pb][k8 + 48][grp];
            float v7 = red[pb][k8 + 56][grp];
            acc = ((v0 + v1) + (v2 + v3)) + ((v4 + v5) + (v6 + v7));
        }
        acc += __shfl_xor_sync(0xffffffffu, acc, 1);
        acc += __shfl_xor_sync(0xffffffffu, acc, 2);
        acc += __shfl_xor_sync(0xffffffffu, acc, 4);
        if (k8 == 0) fin[pb][grp] = acc;

        __syncthreads();   // bar2: fin ready

        {
            float4 pv = *(const float4*)&fin[pb][0];   // broadcast LDS.128
            p0 = pv.x; p1 = pv.y; p2 = pv.z; p3 = pv.w;
        }
        if (tid == 0) {
            float4 qv = *(const float4*)&fin[pb][4];
            outb[(size_t)t * OUT_ + 0] = qv.x + bo0;
            outb[(size_t)t * OUT_ + 1] = qv.y + bo1;
            outb[(size_t)t * OUT_ + 2] = qv.z + bo2;
        }
    }

    // h_last
    *(float4*)(hlast + (size_t)b * HID_ + j0)     = make_float4(h[0], h[1], h[2], h[3]);
    *(float4*)(hlast + (size_t)b * HID_ + j0 + 4) = make_float4(h[4], h[5], h[6], h[7]);
}

extern "C" void kernel_launch(void* const* d_in, const int* in_sizes, int n_in,
                              void* d_out, int out_size) {
    const float* x      = (const float*)d_in[0];
    const float* hidden = (const float*)d_in[1];
    const float* U      = (const float*)d_in[2];
    const float* V      = (const float*)d_in[3];
    const float* Win    = (const float*)d_in[4];
    const float* bin    = (const float*)d_in[5];
    const float* Wout   = (const float*)d_in[6];
    const float* bout   = (const float*)d_in[7];

    float* out   = (float*)d_out;                       // [B,T,OUT]
    float* hlast = out   + (size_t)B_ * T_ * OUT_;      // [B,HID]
    float* rout  = hlast + (size_t)B_ * HID_;           // [B,T,HID]

    low_rank_rnn_kernel<<<B_, TPB>>>(x, hidden, U, V, Win, bin, Wout, bout,
                                     out, hlast, rout);
}